// round 12
// baseline (speedup 1.0000x reference)
#include <cuda_runtime.h>

#define NQ    12
#define DEPTH 6
#define TPB   128
#define MAXP  18

typedef unsigned int u32;

// ---------------------------------------------------------------------------
// Wire q <-> flat-index bit (11-q). CNOT ring = GF(2)-linear index map F
// (Fmap below; Finvmap = F^{-1}). Frame-free storage: sv[swz(r)] holds raw
// index r; after d rings, layer-d gate on bit m is the generalized-qubit gate
//   v = F^d e_m (pairing direction),  f = row m of F^{-d} (selection functional)
// Measurement after the 6th ring: logical index of raw r is F^{-6} r.
// Two gates commute iff f1(v2)=0 and f2(v1)=0.
// ---------------------------------------------------------------------------
__host__ __device__ constexpr u32 Fmap(u32 b) {
    for (int g = 11; g >= 0; --g) {
        int c = 11 - g, t = (c + 11) % NQ;
        b ^= ((b >> c) & 1u) << t;
    }
    return b;
}
__host__ __device__ constexpr u32 Finvmap(u32 b) {
    for (int g = 0; g < NQ; ++g) {
        int c = 11 - g, t = (c + 11) % NQ;
        b ^= ((b >> c) & 1u) << t;
    }
    return b;
}
__host__ __device__ constexpr u32 swz(u32 x) { return x ^ ((x >> 5) & 31u); }
__host__ __device__ constexpr int par(u32 x) {
    x ^= x >> 16; x ^= x >> 8; x ^= x >> 4; x ^= x >> 2; x ^= x >> 1;
    return (int)(x & 1u);
}
__host__ __device__ constexpr u32 W6(u32 x) {
    for (int i = 0; i < 6; ++i) x = Finvmap(x);
    return x;
}

// Incremental GF(2) echelon basis (independence test; mutates only on accept).
struct Elim {
    u32 rows[12]; int n;
    __host__ __device__ constexpr Elim() : rows{}, n(0) {}
    __host__ __device__ constexpr bool add(u32 v) {
        for (int i = 0; i < n; ++i) {
            u32 r = rows[i], hb = 1u << 11;
            while (!(r & hb)) hb >>= 1;
            if (v & hb) v ^= r;
        }
        if (!v) return false;
        rows[n++] = v;
        return true;
    }
};

struct Sched {
    int npass;
    int cnt[MAXP];      // gates in pass (<=5)
    int gidx[MAXP][5];  // gate matrix index d*NQ+m
    u32 gdir[MAXP][5];  // swizzled register dirs (first cnt carry gates)
    u32 fill[MAXP][7];  // swizzled thread-bit dirs (in ∩ null(f_i))
    u32 wdir[5];        // W6 of last pass register dirs (raw)
    u32 wfill[7];       // W6 of last pass fill dirs (raw)
};
__host__ __device__ constexpr Sched mk_sched() {
    Sched S{};
    u32 V[6][12] = {}, FN[6][12] = {}, IC[6][12] = {};
    for (int m = 0; m < 12; ++m) V[0][m] = 1u << m;
    for (int d = 1; d < 6; ++d)
        for (int m = 0; m < 12; ++m) V[d][m] = Fmap(V[d-1][m]);
    for (int j = 0; j < 12; ++j) IC[0][j] = 1u << j;
    for (int d = 1; d < 6; ++d)
        for (int j = 0; j < 12; ++j) IC[d][j] = Finvmap(IC[d-1][j]);
    for (int d = 1; d < 6; ++d)
        for (int m = 0; m < 12; ++m) {
            u32 fv = 0;
            for (int j = 0; j < 12; ++j)
                if ((IC[d][j] >> m) & 1u) fv |= 1u << j;   // (F^{-d})_{m,j}
            FN[d][m] = fv;
        }
    bool used[6][12] = {};
    int remaining = 60, P = 0;
    u32 lastreg[5] = {}, lastfill[7] = {};
    while (remaining > 0) {                   // P>=MAXP -> constexpr OOB error
        Elim E;
        u32 pv[5] = {}, pf[5] = {};
        int c = 0;
        for (int d = 1; d < 6 && c < 5; ++d)
            for (int m = 11; m >= 0 && c < 5; --m) {   // m DESCENDING
                if (used[d][m]) continue;
                u32 v = V[d][m], f = FN[d][m];
                bool ok = true;
                for (int i = 0; i < c; ++i)
                    if (par(pf[i] & v) || par(f & pv[i])) { ok = false; break; }
                if (ok)
                    for (int d2 = 1; d2 < d && ok; ++d2)
                        for (int m2 = 0; m2 < 12 && ok; ++m2)
                            if (!used[d2][m2] &&
                                (par(FN[d2][m2] & v) || par(f & V[d2][m2])))
                                ok = false;
                if (!ok) continue;
                if (!E.add(v)) continue;
                used[d][m] = true; --remaining;
                pv[c] = v; pf[c] = f;
                S.gidx[P][c] = d * NQ + m;
                S.gdir[P][c] = swz(v);
                ++c;
            }
        S.cnt[P] = c;
        // ---- null space of the c functionals (RREF + free columns) --------
        u32 R[5] = {};
        for (int i = 0; i < c; ++i) R[i] = pf[i];
        int pivcol[5] = {}; bool ispiv[12] = {}; int nrows = 0;
        for (int col = 0; col < 12 && nrows < c; ++col) {
            int sel = -1;
            for (int r = nrows; r < c; ++r)
                if ((R[r] >> col) & 1u) { sel = r; break; }
            if (sel < 0) continue;
            u32 tmp = R[nrows]; R[nrows] = R[sel]; R[sel] = tmp;
            for (int r = 0; r < c; ++r)
                if (r != nrows && ((R[r] >> col) & 1u)) R[r] ^= R[nrows];
            pivcol[nrows] = col; ispiv[col] = true; ++nrows;
        }
        u32 ns[12] = {}; int nn = 0;
        for (int j = 0; j < 12; ++j) {
            if (ispiv[j]) continue;
            u32 x = 1u << j;
            for (int r = 0; r < nrows; ++r)
                if ((R[r] >> j) & 1u) x |= 1u << pivcol[r];
            ns[nn++] = x;
        }
        // ---- assign: (5-c) extra register dirs + 7 fill dirs, all in N -----
        u32 regraw[5] = {};
        for (int i = 0; i < c; ++i) regraw[i] = pv[i];
        int k = 0;
        for (int i = c; i < 5; ++i) { regraw[i] = ns[k]; S.gdir[P][i] = swz(ns[k]); ++k; }
        u32 fillraw[7] = {};
        for (int j = 0; j < 7; ++j) { fillraw[j] = ns[k]; S.fill[P][j] = swz(ns[k]); ++k; }
        for (int i = 0; i < 5; ++i) lastreg[i] = regraw[i];
        for (int j = 0; j < 7; ++j) lastfill[j] = fillraw[j];
        ++P;
    }
    S.npass = P;
    for (int i = 0; i < 5; ++i) S.wdir[i]  = W6(lastreg[i]);
    for (int j = 0; j < 7; ++j) S.wfill[j] = W6(lastfill[j]);
    return S;
}
__constant__ Sched SCH = mk_sched();

__device__ __forceinline__ float2 cmul(float2 a, float2 b) {
    return make_float2(fmaf(a.x, b.x, -a.y * b.y), fmaf(a.x, b.y, a.y * b.x));
}

__global__ void __launch_bounds__(TPB, 4)
qsim_kernel(const float* __restrict__ inp, const float* __restrict__ wp,
            float* __restrict__ out)
{
    __shared__ float2 sv[1 << NQ];               // 32 KB state
    __shared__ float2 gms[DEPTH * NQ * 2];       // m00,m01 per gate (SU(2))
    __shared__ float2 vtab[NQ][2];               // per-qubit prep 2-vectors
    __shared__ float  red[TPB / 32];

    const int t   = threadIdx.x;
    const int bid = blockIdx.x;

    // ---- per-block prep ----------------------------------------------------
    if (t < NQ) {
        // fold encode RY(x) with layer-1 Rot into one complex 2-vector/qubit
        float x = inp[bid * NQ + (11 - t)];      // bit t <- wire 11-t
        float sx, cx; sincosf(0.5f * x, &sx, &cx);
        int wo = (11 - t) * 3;                   // w[0][wire]
        float phi = wp[wo + 0], th = wp[wo + 1], om = wp[wo + 2];
        float st, ct; sincosf(0.5f * th, &st, &ct);
        float sa, ca; sincosf(0.5f * (phi + om), &sa, &ca);
        float sb, cb; sincosf(0.5f * (phi - om), &sb, &cb);
        float2 m00 = make_float2( ct * ca, -ct * sa);
        float2 m01 = make_float2(-st * cb, -st * sb);
        float2 m10 = make_float2( st * cb, -st * sb);   // = -conj(m01)
        float2 m11 = make_float2( ct * ca,  ct * sa);   // =  conj(m00)
        vtab[t][0] = make_float2(fmaf(m00.x, cx, m01.x * sx), fmaf(m00.y, cx, m01.y * sx));
        vtab[t][1] = make_float2(fmaf(m10.x, cx, m11.x * sx), fmaf(m10.y, cx, m11.y * sx));
    } else if (t < DEPTH * NQ) {
        // gate matrices for layers 2..6 (d = 1..5); SU(2): keep m00,m01 only
        int d = t / NQ, m = t % NQ;              // m = bit index, wire = 11-m
        int wo = (d * NQ + (11 - m)) * 3;
        float phi = wp[wo + 0], th = wp[wo + 1], om = wp[wo + 2];
        float st, ct; sincosf(0.5f * th, &st, &ct);
        float sa, ca; sincosf(0.5f * (phi + om), &sa, &ca);
        float sb, cb; sincosf(0.5f * (phi - om), &sb, &cb);
        gms[t * 2 + 0] = make_float2( ct * ca, -ct * sa);   // m00
        gms[t * 2 + 1] = make_float2(-st * cb, -st * sb);   // m01
    }
    __syncthreads();

    // ---- prep pass: psi_1 (encode + layer-1 Rot) in identity frame ---------
    {
        u32 pb = 0;
        #pragma unroll
        for (int j = 0; j < 7; ++j)
            if ((t >> j) & 1) pb ^= swz(1u << (5 + j));
        float2 f = vtab[5][t & 1];
        #pragma unroll
        for (int j = 1; j < 7; ++j) f = cmul(f, vtab[5 + j][(t >> j) & 1]);
        float2 v[32]; v[0] = f;
        #pragma unroll
        for (int j = 0; j < 5; ++j) {
            #pragma unroll
            for (int k = 0; k < (1 << j); ++k) {
                float2 lo = v[k];
                v[k]            = cmul(lo, vtab[j][0]);
                v[k + (1 << j)] = cmul(lo, vtab[j][1]);
            }
        }
        #pragma unroll
        for (int c = 0; c < 32; ++c) {
            u32 a = pb;
            if (c & 1)  a ^= swz(1u << 0);
            if (c & 2)  a ^= swz(1u << 1);
            if (c & 4)  a ^= swz(1u << 2);
            if (c & 8)  a ^= swz(1u << 3);
            if (c & 16) a ^= swz(1u << 4);
            sv[a] = v[c];
        }
        __syncthreads();
    }

    float acc = 0.f;
    const int np = SCH.npass;

    // ---- packed passes -----------------------------------------------------
    #pragma unroll 1
    for (int P = 0; P < np; ++P) {
        u32 pb = 0;
        #pragma unroll
        for (int j = 0; j < 7; ++j)
            if ((t >> j) & 1) pb ^= SCH.fill[P][j];
        u32 qd[5];
        #pragma unroll
        for (int k = 0; k < 5; ++k) qd[k] = SCH.gdir[P][k];
        const int cp = SCH.cnt[P];

        float2 s[32];
        #pragma unroll
        for (int c = 0; c < 32; ++c) {
            u32 a = pb;
            if (c & 1)  a ^= qd[0];
            if (c & 2)  a ^= qd[1];
            if (c & 4)  a ^= qd[2];
            if (c & 8)  a ^= qd[3];
            if (c & 16) a ^= qd[4];
            s[c] = sv[a];
        }

        // ---- up to 5 register-resident SU(2) gates -------------------------
        #pragma unroll
        for (int g = 0; g < 5; ++g) {
            if (g < cp) {
                const float2* g2 = &gms[SCH.gidx[P][g] * 2];
                float2 u = g2[0], v = g2[1];                // m00, m01
                #pragma unroll
                for (int c = 0; c < 32; ++c) {
                    if (!((c >> g) & 1)) {
                        float2 a0 = s[c], a1 = s[c | (1 << g)];
                        float2 n0, n1;
                        n0.x = fmaf(u.x, a0.x, fmaf(-u.y, a0.y, fmaf(v.x, a1.x, -v.y * a1.y)));
                        n0.y = fmaf(u.x, a0.y, fmaf( u.y, a0.x, fmaf(v.x, a1.y,  v.y * a1.x)));
                        n1.x = fmaf(u.x, a1.x, fmaf( u.y, a1.y, fmaf(-v.x, a0.x, -v.y * a0.y)));
                        n1.y = fmaf(u.x, a1.y, fmaf(-u.y, a1.x, fmaf( v.y, a0.x, -v.x * a0.y)));
                        s[c] = n0; s[c | (1 << g)] = n1;
                    }
                }
            }
        }

        if (P == np - 1) {
            // ---- fold final ring + <Z> mean into the reduction -------------
            u32 fb = 0;
            #pragma unroll
            for (int j = 0; j < 7; ++j)
                if ((t >> j) & 1) fb ^= SCH.wfill[j];
            u32 fd[5];
            #pragma unroll
            for (int k = 0; k < 5; ++k) fd[k] = SCH.wdir[k];
            #pragma unroll
            for (int c = 0; c < 32; ++c) {
                u32 fv = fb;
                if (c & 1)  fv ^= fd[0];
                if (c & 2)  fv ^= fd[1];
                if (c & 4)  fv ^= fd[2];
                if (c & 8)  fv ^= fd[3];
                if (c & 16) fv ^= fd[4];
                float wgt = (float)(NQ - 2 * __popc(fv));
                acc = fmaf(fmaf(s[c].x, s[c].x, s[c].y * s[c].y), wgt, acc);
            }
        } else {
            #pragma unroll
            for (int c = 0; c < 32; ++c) {
                u32 a = pb;
                if (c & 1)  a ^= qd[0];
                if (c & 2)  a ^= qd[1];
                if (c & 4)  a ^= qd[2];
                if (c & 8)  a ^= qd[3];
                if (c & 16) a ^= qd[4];
                sv[a] = s[c];
            }
            __syncthreads();
        }
    }

    // ---- block reduction -> out[bid] ----
    #pragma unroll
    for (int o = 16; o; o >>= 1) acc += __shfl_xor_sync(0xffffffffu, acc, o);
    if ((t & 31) == 0) red[t >> 5] = acc;
    __syncthreads();
    if (t == 0)
        out[bid] = (red[0] + red[1] + red[2] + red[3]) * (1.0f / NQ);
}

extern "C" void kernel_launch(void* const* d_in, const int* in_sizes, int n_in,
                              void* d_out, int out_size)
{
    const float *inp, *wp;
    if (in_sizes[0] == DEPTH * NQ * 3) {            // defensive input-order check
        wp  = (const float*)d_in[0];
        inp = (const float*)d_in[1];
    } else {
        inp = (const float*)d_in[0];
        wp  = (const float*)d_in[1];
    }
    int B = out_size;                                // [B,1] float output
    qsim_kernel<<<B, TPB>>>(inp, wp, (float*)d_out);
}